// round 8
// baseline (speedup 1.0000x reference)
#include <cuda_runtime.h>

// Problem shape (fixed by reference setup_inputs)
#define NC   19
#define HWX  (512 * 1024)     // 524288 = 2^19
#define NPIX (4 * HWX)        // 2097152 = 2^21
#define MIN_KEPT_K 100000

#define GRID  512
#define BLOCK 256
#define PPB   (NPIX / GRID)        // 4096 pixels per block
#define ITERS (PPB / (BLOCK * 4))  // 4 iterations of 4 pixels/thread
#define SCAN_I (PPB / BLOCK)       // 16 smem elements per thread per scan

// ---------------- device scratch (no allocations allowed) ----------------
__device__ unsigned int g_h[4][256];    // per-round merged histograms
__device__ unsigned int g_cnt[8];       // grid-barrier counters (self-resetting)
__device__ unsigned int g_nvalid;
__device__ double       g_total_sum;    // fallback mean numerator
__device__ double       g_kept_sum;
__device__ unsigned int g_kept_cnt;

// ---------------- init (tiny, per graph replay) ----------------
__global__ void init_kernel() {
    const int t = threadIdx.x;
    g_h[0][t] = 0u; g_h[1][t] = 0u; g_h[2][t] = 0u; g_h[3][t] = 0u;
    if (t < 8) g_cnt[t] = 0u;
    if (t == 0) {
        g_nvalid = 0u; g_total_sum = 0.0; g_kept_sum = 0.0; g_kept_cnt = 0u;
    }
}

// ---------------- grid barrier (all blocks resident by construction) -----
__device__ __forceinline__ void gbar(int i) {
    __syncthreads();
    if (threadIdx.x == 0) {
        __threadfence();
        atomicAdd(&g_cnt[i], 1u);
        while (*((volatile unsigned int*)&g_cnt[i]) < (unsigned)GRID) {}
        __threadfence();
    }
    __syncthreads();
}

// Redundant per-block radix-digit select over a 256-bin global histogram.
// All blocks compute the identical (digit, k_remaining). ss: 256-word scratch.
__device__ __forceinline__ void sel256(const unsigned int* gh, unsigned int k,
                                       unsigned int* ss,
                                       unsigned int* s_dig, unsigned int* s_k,
                                       unsigned int& dig, unsigned int& krem) {
    const int t = threadIdx.x;
    if (t == 0) { *s_dig = 0u; *s_k = 1u; }        // defaults (nv==0 robustness)
    const unsigned int h = *((volatile const unsigned int*)&gh[t]);
    ss[t] = h;
    __syncthreads();
    #pragma unroll
    for (int off = 1; off < 256; off <<= 1) {      // inclusive suffix sum
        unsigned int v = (t + off < 256) ? ss[t + off] : 0u;
        __syncthreads();
        ss[t] += v;
        __syncthreads();
    }
    const unsigned int incl  = ss[t];
    const unsigned int above = incl - h;
    if (above < k && incl >= k) { *s_dig = (unsigned)t; *s_k = k - above; }
    __syncthreads();
    dig  = *s_dig;
    krem = *s_k;
    __syncthreads();
}

// ---------------- the persistent kernel ----------------
__global__ void __launch_bounds__(BLOCK, 4) ohem_kernel(
    const float* __restrict__ logits,
    const int*   __restrict__ targets,     // int32 (jax x64 disabled)
    float*       __restrict__ out)
{
    __shared__ float        sl[PPB];       // this block's losses (16 KB)
    __shared__ unsigned int sh[256];
    __shared__ unsigned int ss[256];
    __shared__ unsigned int s_dig, s_k;
    __shared__ float        rs[8];
    __shared__ int          rc[8];

    const int t = threadIdx.x;
    const int b = blockIdx.x;

    sh[t] = 0u;
    __syncthreads();

    // ---- phase 1: compute losses into smem; local 8-bit hist + stats ----
    float lsum = 0.0f;
    int   lval = 0;
    #pragma unroll
    for (int j = 0; j < ITERS; j++) {
        const int p  = b * PPB + j * (BLOCK * 4) + t * 4;
        const int n  = p >> 19;
        const int hw = p & (HWX - 1);
        const float* base = logits + ((size_t)n * NC) * HWX + hw;
        const int4 tg = *reinterpret_cast<const int4*>(targets + p);

        float4 s  = make_float4(0.f, 0.f, 0.f, 0.f);
        float4 xt = make_float4(0.f, 0.f, 0.f, 0.f);   // tg in [0,NC) -> set once
        #pragma unroll
        for (int c = 0; c < NC; c++) {
            const float4 v = __ldg(reinterpret_cast<const float4*>(base + (size_t)c * HWX));
            s.x += __expf(v.x);  s.y += __expf(v.y);
            s.z += __expf(v.z);  s.w += __expf(v.w);
            xt.x = (tg.x == c) ? v.x : xt.x;
            xt.y = (tg.y == c) ? v.y : xt.y;
            xt.z = (tg.z == c) ? v.z : xt.z;
            xt.w = (tg.w == c) ? v.w : xt.w;
        }
        const float l0 = __logf(s.x) - xt.x;
        const float l1 = __logf(s.y) - xt.y;
        const float l2 = __logf(s.z) - xt.z;
        const float l3 = __logf(s.w) - xt.w;

        *reinterpret_cast<float4*>(&sl[j * (BLOCK * 4) + t * 4]) =
            make_float4(l0, l1, l2, l3);

        if (l0 > 0.0f) { atomicAdd(&sh[__float_as_uint(l0) >> 24], 1u); lval++; }
        if (l1 > 0.0f) { atomicAdd(&sh[__float_as_uint(l1) >> 24], 1u); lval++; }
        if (l2 > 0.0f) { atomicAdd(&sh[__float_as_uint(l2) >> 24], 1u); lval++; }
        if (l3 > 0.0f) { atomicAdd(&sh[__float_as_uint(l3) >> 24], 1u); lval++; }
        lsum += l0 + l1 + l2 + l3;
    }

    // block-reduce lsum / lval
    #pragma unroll
    for (int o = 16; o; o >>= 1) {
        lsum += __shfl_down_sync(0xffffffffu, lsum, o);
        lval += __shfl_down_sync(0xffffffffu, lval, o);
    }
    if ((t & 31) == 0) { rs[t >> 5] = lsum; rc[t >> 5] = lval; }
    __syncthreads();
    if (t < 8) {
        float x = rs[t]; int y = rc[t];
        #pragma unroll
        for (int o = 4; o; o >>= 1) {
            x += __shfl_down_sync(0xffu, x, o);
            y += __shfl_down_sync(0xffu, y, o);
        }
        if (t == 0) {
            if (y) atomicAdd(&g_nvalid, (unsigned)y);
            atomicAdd(&g_total_sum, (double)x);
        }
    }
    if (sh[t]) atomicAdd(&g_h[0][t], sh[t]);   // sparse merge (few nonzero bins)

    gbar(0);

    // ---- phase 2: 4-round radix select (redundant per block) ----
    const unsigned int nv = *((volatile unsigned int*)&g_nvalid);
    unsigned int k;
    {
        int nk = (int)(0.7f * (float)nv);      // f32 mul + trunc, matches jax
        if (nk < MIN_KEPT_K) nk = MIN_KEPT_K;
        if ((unsigned)nk > nv) nk = (int)nv;
        if (nk < 1) nk = 1;
        k = (unsigned)nk;
    }

    unsigned int dig, pref;
    sel256(g_h[0], k, ss, &s_dig, &s_k, dig, k);
    pref = dig;

    #pragma unroll
    for (int r = 1; r < 4; r++) {
        const int shm = 24 - 8 * r;            // 16, 8, 0
        sh[t] = 0u;
        __syncthreads();
        #pragma unroll
        for (int i = 0; i < SCAN_I; i++) {
            const float v = sl[i * BLOCK + t];
            if (v > 0.0f) {
                const unsigned int bb = __float_as_uint(v);
                if ((bb >> (shm + 8)) == pref)
                    atomicAdd(&sh[(bb >> shm) & 255u], 1u);
            }
        }
        __syncthreads();
        if (sh[t]) atomicAdd(&g_h[r][t], sh[t]);
        gbar(r);
        sel256(g_h[r], k, ss, &s_dig, &s_k, dig, k);
        pref = (pref << 8) | dig;
    }

    // ---- phase 3: masked sum/count over smem losses ----
    const float fth = __uint_as_float(pref);   // exact k-th-largest (> 0)
    float s = 0.0f;
    int   c = 0;
    #pragma unroll
    for (int i = 0; i < SCAN_I; i++) {
        const float v = sl[i * BLOCK + t];
        if (v >= fth) { s += v; c++; }
    }
    #pragma unroll
    for (int o = 16; o; o >>= 1) {
        s += __shfl_down_sync(0xffffffffu, s, o);
        c += __shfl_down_sync(0xffffffffu, c, o);
    }
    if ((t & 31) == 0) { rs[t >> 5] = s; rc[t >> 5] = c; }
    __syncthreads();
    if (t < 8) {
        float x = rs[t]; int y = rc[t];
        #pragma unroll
        for (int o = 4; o; o >>= 1) {
            x += __shfl_down_sync(0xffu, x, o);
            y += __shfl_down_sync(0xffu, y, o);
        }
        if (t == 0) {
            atomicAdd(&g_kept_sum, (double)x);
            if (y) atomicAdd(&g_kept_cnt, (unsigned)y);
        }
    }
    __syncthreads();

    // ---- final: arrive-only barrier; block 0 finalizes + resets ----
    if (t == 0) {
        __threadfence();
        atomicAdd(&g_cnt[4], 1u);
        if (b == 0) {
            while (*((volatile unsigned int*)&g_cnt[4]) < (unsigned)GRID) {}
            __threadfence();
            if (nv > 0u) {
                unsigned int kc = *((volatile unsigned int*)&g_kept_cnt);
                if (kc == 0u) kc = 1u;
                const double ks = *((volatile double*)&g_kept_sum);
                out[0] = (float)(ks / (double)kc);
            } else {
                out[0] = (float)(*((volatile double*)&g_total_sum) / (double)NPIX);
            }
            // self-reset barrier counters for the next graph replay
            #pragma unroll
            for (int i = 0; i < 8; i++) g_cnt[i] = 0u;
        }
    }
}

// ---------------- entry point ----------------
extern "C" void kernel_launch(void* const* d_in, const int* in_sizes, int n_in,
                              void* d_out, int out_size) {
    const float* logits  = (const float*)d_in[0];
    const int*   targets = (const int*)d_in[1];
    float*       out     = (float*)d_out;

    init_kernel<<<1, 256>>>();
    ohem_kernel<<<GRID, BLOCK>>>(logits, targets, out);
}